// round 5
// baseline (speedup 1.0000x reference)
#include <cuda_runtime.h>
#include <cstdint>

#define DIM 2048
#define HID 1024
#define NEXP 8
#define TOTAL 16384
#define LDA 36   // padded u32 stride (conflict-free, 16B-aligned)

// 64MB scratch for h = silu(x@G^T) * (x@U^T)
__device__ float g_hbuf[(size_t)TOTAL * HID];

__device__ __forceinline__ uint32_t f2tf32(float x) {
    uint32_t r;
    asm("cvt.rna.tf32.f32 %0, %1;" : "=r"(r) : "f"(x));
    return r;
}

__device__ __forceinline__ void mma_tf32(float c[4], const uint32_t a[4], const uint32_t b[2]) {
    asm volatile(
        "mma.sync.aligned.m16n8k8.row.col.f32.tf32.tf32.f32 "
        "{%0,%1,%2,%3}, {%4,%5,%6,%7}, {%8,%9}, {%0,%1,%2,%3};"
        : "+f"(c[0]), "+f"(c[1]), "+f"(c[2]), "+f"(c[3])
        : "r"(a[0]), "r"(a[1]), "r"(a[2]), "r"(a[3]), "r"(b[0]), "r"(b[1]));
}

__device__ __forceinline__ int expert_of(const int* __restrict__ counts, int row0) {
    int e = 0, acc = 0;
#pragma unroll
    for (int i = 0; i < NEXP; i++) {
        if (row0 >= acc) e = i;
        acc += counts[i];
    }
    return e;
}

__device__ __forceinline__ void st_cvt4(uint32_t* dst, float4 v) {
    uint4 w = make_uint4(f2tf32(v.x), f2tf32(v.y), f2tf32(v.z), f2tf32(v.w));
    *reinterpret_cast<uint4*>(dst) = w;
}

// ---------------------------------------------------------------------------
// Kernel 1: fused gate+up + SwiGLU. BM=128, BN=64 (per matrix), BK=32.
// 512 threads = 16 warps (4M x 4N), warp tile 32x16 per matrix (mi=2, ni=2).
// Double-buffered smem: per buf A 128x36, G 64x36, U 64x36 (u32).
// ---------------------------------------------------------------------------
#define GU_BUF (128*LDA + 64*LDA + 64*LDA)   // 9216 u32 per buffer
__global__ __launch_bounds__(512, 1) void gateup_kernel(
    const float* __restrict__ x,
    const float* __restrict__ gate,
    const float* __restrict__ up,
    const int* __restrict__ counts)
{
    extern __shared__ uint32_t sm[];

    const int tid  = threadIdx.x;
    const int lane = tid & 31;
    const int warp = tid >> 5;          // 0..15
    const int gid  = lane >> 2;
    const int tg   = lane & 3;
    const int wm   = (warp >> 2) * 32;  // 4 M-groups
    const int wn   = (warp & 3) * 16;   // 4 N-groups of 16

    const int row0 = blockIdx.y * 128;
    const int n0   = blockIdx.x * 64;
    const int e = expert_of(counts, row0);

    const float* Ap = x    + (size_t)row0 * DIM;
    const float* Gp = gate + (size_t)e * HID * DIM + (size_t)n0 * DIM;
    const float* Up = up   + (size_t)e * HID * DIM + (size_t)n0 * DIM;

    float4 ra[2], rg, ru;

    auto gload = [&](int k0) {
#pragma unroll
        for (int i = 0; i < 2; i++) {
            int f = i * 512 + tid; int r = f >> 3; int c = (f & 7) * 4;
            ra[i] = *reinterpret_cast<const float4*>(Ap + (size_t)r * DIM + k0 + c);
        }
        {
            int r = tid >> 3; int c = (tid & 7) * 4;
            rg = *reinterpret_cast<const float4*>(Gp + (size_t)r * DIM + k0 + c);
            ru = *reinterpret_cast<const float4*>(Up + (size_t)r * DIM + k0 + c);
        }
    };
    auto stage = [&](int buf) {
        uint32_t* As = sm + buf * GU_BUF;
        uint32_t* Gs = As + 128 * LDA;
        uint32_t* Us = Gs + 64 * LDA;
#pragma unroll
        for (int i = 0; i < 2; i++) {
            int f = i * 512 + tid; int r = f >> 3; int c = (f & 7) * 4;
            st_cvt4(&As[r * LDA + c], ra[i]);
        }
        {
            int r = tid >> 3; int c = (tid & 7) * 4;
            st_cvt4(&Gs[r * LDA + c], rg);
            st_cvt4(&Us[r * LDA + c], ru);
        }
    };

    float accg[2][2][4] = {};
    float accu[2][2][4] = {};

    gload(0);
    stage(0);
    __syncthreads();

    const int NK = DIM / 32;
    for (int kt = 0; kt < NK; kt++) {
        if (kt + 1 < NK) gload((kt + 1) * 32);

        const uint32_t* As = sm + (kt & 1) * GU_BUF;
        const uint32_t* Gs = As + 128 * LDA;
        const uint32_t* Us = Gs + 64 * LDA;
#pragma unroll
        for (int kk8 = 0; kk8 < 4; kk8++) {
            const int kk = kk8 * 8;
            uint32_t af[2][4];
#pragma unroll
            for (int mi = 0; mi < 2; mi++) {
                int r = wm + mi * 16 + gid;
                af[mi][0] = As[r * LDA + kk + tg];
                af[mi][1] = As[(r + 8) * LDA + kk + tg];
                af[mi][2] = As[r * LDA + kk + tg + 4];
                af[mi][3] = As[(r + 8) * LDA + kk + tg + 4];
            }
#pragma unroll
            for (int ni = 0; ni < 2; ni++) {
                int rb = wn + ni * 8 + gid;
                uint32_t bg[2] = { Gs[rb * LDA + kk + tg], Gs[rb * LDA + kk + tg + 4] };
                uint32_t bu[2] = { Us[rb * LDA + kk + tg], Us[rb * LDA + kk + tg + 4] };
#pragma unroll
                for (int mi = 0; mi < 2; mi++) {
                    mma_tf32(accg[mi][ni], af[mi], bg);
                    mma_tf32(accu[mi][ni], af[mi], bu);
                }
            }
        }
        if (kt + 1 < NK) stage((kt + 1) & 1);
        __syncthreads();
    }

    // SwiGLU epilogue, float2 stores
#pragma unroll
    for (int mi = 0; mi < 2; mi++)
#pragma unroll
        for (int ni = 0; ni < 2; ni++) {
            int r = row0 + wm + mi * 16 + gid;
            int c = n0 + wn + ni * 8 + tg * 2;
            float g0 = accg[mi][ni][0], u0 = accu[mi][ni][0];
            float g1 = accg[mi][ni][1], u1 = accu[mi][ni][1];
            float g2 = accg[mi][ni][2], u2 = accu[mi][ni][2];
            float g3 = accg[mi][ni][3], u3 = accu[mi][ni][3];
            float2 h0 = make_float2(g0 * u0 / (1.0f + __expf(-g0)),
                                    g1 * u1 / (1.0f + __expf(-g1)));
            float2 h1 = make_float2(g2 * u2 / (1.0f + __expf(-g2)),
                                    g3 * u3 / (1.0f + __expf(-g3)));
            *reinterpret_cast<float2*>(&g_hbuf[(size_t)r * HID + c]) = h0;
            *reinterpret_cast<float2*>(&g_hbuf[(size_t)(r + 8) * HID + c]) = h1;
        }
}

// ---------------------------------------------------------------------------
// Kernel 2: down GEMM. out = h @ D_e^T. M=16384, N=2048, K=1024.
// BM=128, BN=128, BK=32. 512 threads = 16 warps (4M x 4N), warp tile 32x32
// (mi=2, ni=4).
// ---------------------------------------------------------------------------
#define DN_BUF (128*LDA + 128*LDA)   // 9216 u32 per buffer
__global__ __launch_bounds__(512, 1) void down_kernel(
    const float* __restrict__ down,
    const int* __restrict__ counts,
    float* __restrict__ out)
{
    extern __shared__ uint32_t sm[];

    const int tid  = threadIdx.x;
    const int lane = tid & 31;
    const int warp = tid >> 5;          // 0..15
    const int gid  = lane >> 2;
    const int tg   = lane & 3;
    const int wm   = (warp >> 2) * 32;  // 4 M-groups of 32
    const int wn   = (warp & 3) * 32;   // 4 N-groups of 32

    const int row0 = blockIdx.y * 128;
    const int n0   = blockIdx.x * 128;
    const int e = expert_of(counts, row0);

    const float* Ap = g_hbuf + (size_t)row0 * HID;
    const float* Dp = down   + (size_t)e * DIM * HID + (size_t)n0 * HID;

    float4 ra[2], rd[2];

    auto gload = [&](int k0) {
#pragma unroll
        for (int i = 0; i < 2; i++) {
            int f = i * 512 + tid; int r = f >> 3; int c = (f & 7) * 4;
            ra[i] = *reinterpret_cast<const float4*>(Ap + (size_t)r * HID + k0 + c);
            rd[i] = *reinterpret_cast<const float4*>(Dp + (size_t)r * HID + k0 + c);
        }
    };
    auto stage = [&](int buf) {
        uint32_t* As = sm + buf * DN_BUF;
        uint32_t* Ds = As + 128 * LDA;
#pragma unroll
        for (int i = 0; i < 2; i++) {
            int f = i * 512 + tid; int r = f >> 3; int c = (f & 7) * 4;
            st_cvt4(&As[r * LDA + c], ra[i]);
            st_cvt4(&Ds[r * LDA + c], rd[i]);
        }
    };

    float acc[2][4][4] = {};

    gload(0);
    stage(0);
    __syncthreads();

    const int NK = HID / 32;
    for (int kt = 0; kt < NK; kt++) {
        if (kt + 1 < NK) gload((kt + 1) * 32);

        const uint32_t* As = sm + (kt & 1) * DN_BUF;
        const uint32_t* Ds = As + 128 * LDA;
#pragma unroll
        for (int kk8 = 0; kk8 < 4; kk8++) {
            const int kk = kk8 * 8;
            uint32_t af[2][4];
#pragma unroll
            for (int mi = 0; mi < 2; mi++) {
                int r = wm + mi * 16 + gid;
                af[mi][0] = As[r * LDA + kk + tg];
                af[mi][1] = As[(r + 8) * LDA + kk + tg];
                af[mi][2] = As[r * LDA + kk + tg + 4];
                af[mi][3] = As[(r + 8) * LDA + kk + tg + 4];
            }
#pragma unroll
            for (int ni = 0; ni < 4; ni++) {
                int rb = wn + ni * 8 + gid;
                uint32_t bd[2] = { Ds[rb * LDA + kk + tg], Ds[rb * LDA + kk + tg + 4] };
#pragma unroll
                for (int mi = 0; mi < 2; mi++) {
                    mma_tf32(acc[mi][ni], af[mi], bd);
                }
            }
        }
        if (kt + 1 < NK) stage((kt + 1) & 1);
        __syncthreads();
    }

#pragma unroll
    for (int mi = 0; mi < 2; mi++)
#pragma unroll
        for (int ni = 0; ni < 4; ni++) {
            int r = row0 + wm + mi * 16 + gid;
            int c = n0 + wn + ni * 8 + tg * 2;
            *reinterpret_cast<float2*>(&out[(size_t)r * DIM + c]) =
                make_float2(acc[mi][ni][0], acc[mi][ni][1]);
            *reinterpret_cast<float2*>(&out[(size_t)(r + 8) * DIM + c]) =
                make_float2(acc[mi][ni][2], acc[mi][ni][3]);
        }
}

extern "C" void kernel_launch(void* const* d_in, const int* in_sizes, int n_in,
                              void* d_out, int out_size) {
    const float* x      = (const float*)d_in[0];
    const float* gate   = (const float*)d_in[1];
    const float* up     = (const float*)d_in[2];
    const float* down   = (const float*)d_in[3];
    const int*   counts = (const int*)d_in[4];
    float* out = (float*)d_out;

    const int gu_smem = 2 * GU_BUF * 4;   // 73728 B
    const int dn_smem = 2 * DN_BUF * 4;   // 73728 B

    static bool attr_set = false;
    if (!attr_set) {
        cudaFuncSetAttribute(gateup_kernel, cudaFuncAttributeMaxDynamicSharedMemorySize, gu_smem);
        cudaFuncSetAttribute(down_kernel,   cudaFuncAttributeMaxDynamicSharedMemorySize, dn_smem);
        attr_set = true;
    }

    dim3 g1(HID / 64, TOTAL / 128);    // (16, 128)
    gateup_kernel<<<g1, 512, gu_smem>>>(x, gate, up, counts);

    dim3 g2(DIM / 128, TOTAL / 128);   // (16, 128)
    down_kernel<<<g2, 512, dn_smem>>>(down, counts, out);
}

// round 6
// speedup vs baseline: 1.6566x; 1.6566x over previous
#include <cuda_runtime.h>
#include <cuda_fp16.h>
#include <cstdint>

#define DIM 2048
#define HID 1024
#define NEXP 8
#define TOTAL 16384

// 64MB scratch for h = silu(x@G^T) * (x@U^T)
__device__ float g_hbuf[(size_t)TOTAL * HID];

__device__ __forceinline__ uint32_t smem_u32(const void* p) {
    uint32_t a;
    asm("{ .reg .u64 t; cvta.to.shared.u64 t, %1; cvt.u32.u64 %0, t; }" : "=r"(a) : "l"(p));
    return a;
}

__device__ __forceinline__ void ldsm4(uint32_t r[4], uint32_t addr) {
    asm volatile("ldmatrix.sync.aligned.m8n8.x4.shared.b16 {%0,%1,%2,%3}, [%4];"
                 : "=r"(r[0]), "=r"(r[1]), "=r"(r[2]), "=r"(r[3]) : "r"(addr));
}

__device__ __forceinline__ void mma16816(float c[4], const uint32_t a[4], const uint32_t b[2]) {
    asm volatile(
        "mma.sync.aligned.m16n8k16.row.col.f32.f16.f16.f32 "
        "{%0,%1,%2,%3}, {%4,%5,%6,%7}, {%8,%9}, {%0,%1,%2,%3};"
        : "+f"(c[0]), "+f"(c[1]), "+f"(c[2]), "+f"(c[3])
        : "r"(a[0]), "r"(a[1]), "r"(a[2]), "r"(a[3]), "r"(b[0]), "r"(b[1]));
}

__device__ __forceinline__ int expert_of(const int* __restrict__ counts, int row0) {
    int e = 0, acc = 0;
#pragma unroll
    for (int i = 0; i < NEXP; i++) { if (row0 >= acc) e = i; acc += counts[i]; }
    return e;
}

// Tile rows are 128 bytes (64 fp16). chunk = 16B unit (8 halves), XOR-8 swizzle.
__device__ __forceinline__ uint32_t tile_addr(uint32_t base, int row, int chunk) {
    return base + row * 128 + (((chunk ^ (row & 7)) & 7) << 4);
}

// convert 8 f32 (two float4, consecutive k) -> 16B of fp16, store swizzled
__device__ __forceinline__ void st8h(uint32_t base, int row, int kch, float4 lo, float4 hi) {
    __half2 h0 = __float22half2_rn(make_float2(lo.x, lo.y));
    __half2 h1 = __float22half2_rn(make_float2(lo.z, lo.w));
    __half2 h2 = __float22half2_rn(make_float2(hi.x, hi.y));
    __half2 h3 = __float22half2_rn(make_float2(hi.z, hi.w));
    uint32_t a = tile_addr(base, row, kch);
    asm volatile("st.shared.v4.b32 [%0], {%1,%2,%3,%4};"
                 :: "r"(a),
                    "r"(*reinterpret_cast<uint32_t*>(&h0)),
                    "r"(*reinterpret_cast<uint32_t*>(&h1)),
                    "r"(*reinterpret_cast<uint32_t*>(&h2)),
                    "r"(*reinterpret_cast<uint32_t*>(&h3)) : "memory");
}

// ---------------------------------------------------------------------------
// Kernel 1: fused gate+up + SwiGLU. BM=128, BN=64 per matrix, BK=64.
// 512 threads = 16 warps (4M x 4N), warp tile 32x16 per matrix (mi=2, 2 n-blocks).
// smem per buf: A 128x128B (16K) + G 64x128B (8K) + U 8K = 32K; dbuf = 64K.
// ---------------------------------------------------------------------------
#define GU_BUFB 32768
__global__ __launch_bounds__(512, 1) void gateup_kernel(
    const float* __restrict__ x,
    const float* __restrict__ gate,
    const float* __restrict__ up,
    const int* __restrict__ counts)
{
    extern __shared__ __align__(1024) uint8_t smraw[];
    const uint32_t sb = smem_u32(smraw);

    const int tid  = threadIdx.x;
    const int lane = tid & 31;
    const int warp = tid >> 5;
    const int gid  = lane >> 2;
    const int tg   = lane & 3;
    const int wm   = (warp >> 2) * 32;   // 4 M groups of 32
    const int wn   = (warp & 3) * 16;    // 4 N groups of 16 (per matrix)

    const int row0 = blockIdx.y * 128;
    const int n0   = blockIdx.x * 64;
    const int e = expert_of(counts, row0);

    const float* Ap = x    + (size_t)row0 * DIM;
    const float* Gp = gate + (size_t)e * HID * DIM + (size_t)n0 * DIM;
    const float* Up = up   + (size_t)e * HID * DIM + (size_t)n0 * DIM;

    // per-thread staging chunks: A: c = tid, tid+512 (of 1024); G: tid (of 512); U: tid
    float4 raA[2][2], raG[2], raU[2];
    auto gload = [&](int k0) {
#pragma unroll
        for (int i = 0; i < 2; i++) {
            int c = tid + i * 512; int r = c >> 3; int kc = c & 7;
            const float* s = Ap + (size_t)r * DIM + k0 + kc * 8;
            raA[i][0] = *reinterpret_cast<const float4*>(s);
            raA[i][1] = *reinterpret_cast<const float4*>(s + 4);
        }
        {
            int r = tid >> 3; int kc = tid & 7;
            const float* sg = Gp + (size_t)r * DIM + k0 + kc * 8;
            raG[0] = *reinterpret_cast<const float4*>(sg);
            raG[1] = *reinterpret_cast<const float4*>(sg + 4);
            const float* su = Up + (size_t)r * DIM + k0 + kc * 8;
            raU[0] = *reinterpret_cast<const float4*>(su);
            raU[1] = *reinterpret_cast<const float4*>(su + 4);
        }
    };
    auto stage = [&](int buf) {
        const uint32_t Ab = sb + buf * GU_BUFB;
        const uint32_t Gb = Ab + 16384;
        const uint32_t Ub = Gb + 8192;
#pragma unroll
        for (int i = 0; i < 2; i++) {
            int c = tid + i * 512; int r = c >> 3; int kc = c & 7;
            st8h(Ab, r, kc, raA[i][0], raA[i][1]);
        }
        {
            int r = tid >> 3; int kc = tid & 7;
            st8h(Gb, r, kc, raG[0], raG[1]);
            st8h(Ub, r, kc, raU[0], raU[1]);
        }
    };

    float accg[2][2][4] = {};
    float accu[2][2][4] = {};

    gload(0);
    stage(0);
    __syncthreads();

    // ldmatrix lane addressing (computed once)
    const int a_row = (lane & 15);           // + wm + mi*16
    const int a_ch  = (lane >> 4);           // + 2q
    const int b_row = (lane & 7) + ((lane & 16) >> 1);  // + wn
    const int b_ch  = ((lane >> 3) & 1);     // + 2q

    const int NK = DIM / 64;   // 32
    for (int kt = 0; kt < NK; kt++) {
        if (kt + 1 < NK) gload((kt + 1) * 64);

        const uint32_t Ab = sb + (kt & 1) * GU_BUFB;
        const uint32_t Gb = Ab + 16384;
        const uint32_t Ub = Gb + 8192;
#pragma unroll
        for (int q = 0; q < 4; q++) {
            uint32_t af[2][4];
#pragma unroll
            for (int mi = 0; mi < 2; mi++)
                ldsm4(af[mi], tile_addr(Ab, wm + mi * 16 + a_row, 2 * q + a_ch));
            uint32_t gfr[4], ufr[4];
            ldsm4(gfr, tile_addr(Gb, wn + b_row, 2 * q + b_ch));
            ldsm4(ufr, tile_addr(Ub, wn + b_row, 2 * q + b_ch));
#pragma unroll
            for (int ni = 0; ni < 2; ni++) {
                uint32_t bg[2] = { gfr[2 * ni], gfr[2 * ni + 1] };
                uint32_t bu[2] = { ufr[2 * ni], ufr[2 * ni + 1] };
#pragma unroll
                for (int mi = 0; mi < 2; mi++) {
                    mma16816(accg[mi][ni], af[mi], bg);
                    mma16816(accu[mi][ni], af[mi], bu);
                }
            }
        }
        if (kt + 1 < NK) stage((kt + 1) & 1);
        __syncthreads();
    }

    // SwiGLU epilogue
#pragma unroll
    for (int mi = 0; mi < 2; mi++)
#pragma unroll
        for (int ni = 0; ni < 2; ni++) {
            int r = row0 + wm + mi * 16 + gid;
            int c = n0 + wn + ni * 8 + tg * 2;
            float g0 = accg[mi][ni][0], u0 = accu[mi][ni][0];
            float g1 = accg[mi][ni][1], u1 = accu[mi][ni][1];
            float g2 = accg[mi][ni][2], u2 = accu[mi][ni][2];
            float g3 = accg[mi][ni][3], u3 = accu[mi][ni][3];
            float2 h0 = make_float2(g0 * u0 / (1.0f + __expf(-g0)),
                                    g1 * u1 / (1.0f + __expf(-g1)));
            float2 h1 = make_float2(g2 * u2 / (1.0f + __expf(-g2)),
                                    g3 * u3 / (1.0f + __expf(-g3)));
            *reinterpret_cast<float2*>(&g_hbuf[(size_t)r * HID + c]) = h0;
            *reinterpret_cast<float2*>(&g_hbuf[(size_t)(r + 8) * HID + c]) = h1;
        }
}

// ---------------------------------------------------------------------------
// Kernel 2: down GEMM. out = h @ D_e^T. M=16384, N=2048, K=1024.
// BM=128, BN=128, BK=64. 512 threads = 16 warps (4M x 4N), warp tile 32x32
// (mi=2, ni=4). smem per buf: A 16K + D 16K = 32K; dbuf = 64K.
// ---------------------------------------------------------------------------
#define DN_BUFB 32768
__global__ __launch_bounds__(512, 1) void down_kernel(
    const float* __restrict__ down,
    const int* __restrict__ counts,
    float* __restrict__ out)
{
    extern __shared__ __align__(1024) uint8_t smraw[];
    const uint32_t sb = smem_u32(smraw);

    const int tid  = threadIdx.x;
    const int lane = tid & 31;
    const int warp = tid >> 5;
    const int gid  = lane >> 2;
    const int tg   = lane & 3;
    const int wm   = (warp >> 2) * 32;   // 4 M groups of 32
    const int wn   = (warp & 3) * 32;    // 4 N groups of 32

    const int row0 = blockIdx.y * 128;
    const int n0   = blockIdx.x * 128;
    const int e = expert_of(counts, row0);

    const float* Ap = g_hbuf + (size_t)row0 * HID;
    const float* Dp = down   + (size_t)e * DIM * HID + (size_t)n0 * HID;

    float4 raA[2][2], raD[2][2];
    auto gload = [&](int k0) {
#pragma unroll
        for (int i = 0; i < 2; i++) {
            int c = tid + i * 512; int r = c >> 3; int kc = c & 7;
            const float* sa = Ap + (size_t)r * HID + k0 + kc * 8;
            raA[i][0] = *reinterpret_cast<const float4*>(sa);
            raA[i][1] = *reinterpret_cast<const float4*>(sa + 4);
            const float* sd = Dp + (size_t)r * HID + k0 + kc * 8;
            raD[i][0] = *reinterpret_cast<const float4*>(sd);
            raD[i][1] = *reinterpret_cast<const float4*>(sd + 4);
        }
    };
    auto stage = [&](int buf) {
        const uint32_t Ab = sb + buf * DN_BUFB;
        const uint32_t Db = Ab + 16384;
#pragma unroll
        for (int i = 0; i < 2; i++) {
            int c = tid + i * 512; int r = c >> 3; int kc = c & 7;
            st8h(Ab, r, kc, raA[i][0], raA[i][1]);
            st8h(Db, r, kc, raD[i][0], raD[i][1]);
        }
    };

    float acc[2][4][4] = {};

    gload(0);
    stage(0);
    __syncthreads();

    const int a_row = (lane & 15);
    const int a_ch  = (lane >> 4);
    const int b_row = (lane & 7) + ((lane & 16) >> 1);
    const int b_ch  = ((lane >> 3) & 1);

    const int NK = HID / 64;   // 16
    for (int kt = 0; kt < NK; kt++) {
        if (kt + 1 < NK) gload((kt + 1) * 64);

        const uint32_t Ab = sb + (kt & 1) * DN_BUFB;
        const uint32_t Db = Ab + 16384;
#pragma unroll
        for (int q = 0; q < 4; q++) {
            uint32_t af[2][4];
#pragma unroll
            for (int mi = 0; mi < 2; mi++)
                ldsm4(af[mi], tile_addr(Ab, wm + mi * 16 + a_row, 2 * q + a_ch));
            uint32_t bf[4][2];
#pragma unroll
            for (int nj = 0; nj < 2; nj++) {
                uint32_t t4[4];
                ldsm4(t4, tile_addr(Db, wn + nj * 16 + b_row, 2 * q + b_ch));
                bf[2 * nj][0] = t4[0]; bf[2 * nj][1] = t4[1];
                bf[2 * nj + 1][0] = t4[2]; bf[2 * nj + 1][1] = t4[3];
            }
#pragma unroll
            for (int ni = 0; ni < 4; ni++)
#pragma unroll
                for (int mi = 0; mi < 2; mi++)
                    mma16816(acc[mi][ni], af[mi], bf[ni]);
        }
        if (kt + 1 < NK) stage((kt + 1) & 1);
        __syncthreads();
    }

#pragma unroll
    for (int mi = 0; mi < 2; mi++)
#pragma unroll
        for (int ni = 0; ni < 4; ni++) {
            int r = row0 + wm + mi * 16 + gid;
            int c = n0 + wn + ni * 8 + tg * 2;
            *reinterpret_cast<float2*>(&out[(size_t)r * DIM + c]) =
                make_float2(acc[mi][ni][0], acc[mi][ni][1]);
            *reinterpret_cast<float2*>(&out[(size_t)(r + 8) * DIM + c]) =
                make_float2(acc[mi][ni][2], acc[mi][ni][3]);
        }
}

extern "C" void kernel_launch(void* const* d_in, const int* in_sizes, int n_in,
                              void* d_out, int out_size) {
    const float* x      = (const float*)d_in[0];
    const float* gate   = (const float*)d_in[1];
    const float* up     = (const float*)d_in[2];
    const float* down   = (const float*)d_in[3];
    const int*   counts = (const int*)d_in[4];
    float* out = (float*)d_out;

    const int gu_smem = 2 * GU_BUFB;   // 65536
    const int dn_smem = 2 * DN_BUFB;   // 65536

    static bool attr_set = false;
    if (!attr_set) {
        cudaFuncSetAttribute(gateup_kernel, cudaFuncAttributeMaxDynamicSharedMemorySize, gu_smem);
        cudaFuncSetAttribute(down_kernel,   cudaFuncAttributeMaxDynamicSharedMemorySize, dn_smem);
        attr_set = true;
    }

    dim3 g1(HID / 64, TOTAL / 128);    // (16, 128)
    gateup_kernel<<<g1, 512, gu_smem>>>(x, gate, up, counts);

    dim3 g2(DIM / 128, TOTAL / 128);   // (16, 128)
    down_kernel<<<g2, 512, dn_smem>>>(down, counts, out);
}

// round 7
// speedup vs baseline: 2.6126x; 1.5771x over previous
#include <cuda_runtime.h>
#include <cuda_fp16.h>
#include <cstdint>

#define DIM 2048
#define HID 1024
#define NEXP 8
#define TOTAL 16384
#define STAGES 3

// fp16 copies of inputs (converted once per launch) + fp16 h buffer
__device__ __half g_x16[(size_t)TOTAL * DIM];
__device__ __half g_g16[(size_t)NEXP * HID * DIM];
__device__ __half g_u16[(size_t)NEXP * HID * DIM];
__device__ __half g_d16[(size_t)NEXP * DIM * HID];
__device__ __half g_h16[(size_t)TOTAL * HID];

__device__ __forceinline__ uint32_t smem_u32(const void* p) {
    uint32_t a;
    asm("{ .reg .u64 t; cvta.to.shared.u64 t, %1; cvt.u32.u64 %0, t; }" : "=r"(a) : "l"(p));
    return a;
}
__device__ __forceinline__ void ldsm4(uint32_t r[4], uint32_t addr) {
    asm volatile("ldmatrix.sync.aligned.m8n8.x4.shared.b16 {%0,%1,%2,%3}, [%4];"
                 : "=r"(r[0]), "=r"(r[1]), "=r"(r[2]), "=r"(r[3]) : "r"(addr));
}
__device__ __forceinline__ void mma16816(float c[4], const uint32_t a[4], const uint32_t b[2]) {
    asm volatile(
        "mma.sync.aligned.m16n8k16.row.col.f32.f16.f16.f32 "
        "{%0,%1,%2,%3}, {%4,%5,%6,%7}, {%8,%9}, {%0,%1,%2,%3};"
        : "+f"(c[0]), "+f"(c[1]), "+f"(c[2]), "+f"(c[3])
        : "r"(a[0]), "r"(a[1]), "r"(a[2]), "r"(a[3]), "r"(b[0]), "r"(b[1]));
}
__device__ __forceinline__ void cpa16(uint32_t dst, const void* src) {
    asm volatile("cp.async.cg.shared.global [%0], [%1], 16;" :: "r"(dst), "l"(src) : "memory");
}
#define CP_COMMIT() asm volatile("cp.async.commit_group;" ::: "memory")
#define CP_WAIT1()  asm volatile("cp.async.wait_group 1;" ::: "memory")

__device__ __forceinline__ int expert_of(const int* __restrict__ counts, int row0) {
    int e = 0, acc = 0;
#pragma unroll
    for (int i = 0; i < NEXP; i++) { if (row0 >= acc) e = i; acc += counts[i]; }
    return e;
}

// Tile rows are 128 bytes (64 fp16); chunk = 16B unit, XOR-8 swizzle (verified R6).
__device__ __forceinline__ uint32_t tile_addr(uint32_t base, int row, int chunk) {
    return base + row * 128 + (((chunk ^ (row & 7)) & 7) << 4);
}

// ---------------------------------------------------------------------------
// f32 -> fp16 convert (grid-stride, 8 elems/iter)
// ---------------------------------------------------------------------------
__global__ __launch_bounds__(256) void cvt_kernel(const float* __restrict__ src,
                                                  __half* __restrict__ dst, size_t n8)
{
    size_t idx = (size_t)blockIdx.x * blockDim.x + threadIdx.x;
    size_t stride = (size_t)gridDim.x * blockDim.x;
    for (size_t i = idx; i < n8; i += stride) {
        const float4* s = reinterpret_cast<const float4*>(src) + i * 2;
        float4 a = s[0], b = s[1];
        __half2 h0 = __float22half2_rn(make_float2(a.x, a.y));
        __half2 h1 = __float22half2_rn(make_float2(a.z, a.w));
        __half2 h2 = __float22half2_rn(make_float2(b.x, b.y));
        __half2 h3 = __float22half2_rn(make_float2(b.z, b.w));
        uint4 o;
        o.x = *reinterpret_cast<uint32_t*>(&h0);
        o.y = *reinterpret_cast<uint32_t*>(&h1);
        o.z = *reinterpret_cast<uint32_t*>(&h2);
        o.w = *reinterpret_cast<uint32_t*>(&h3);
        reinterpret_cast<uint4*>(dst)[i] = o;
    }
}

// ---------------------------------------------------------------------------
// Kernel 1: gateup. BM=256, BN=64 (gate) + 64 (up), BK=64.
// 256 threads = 8 warps (4M x 2N), warp tile 64x32 per matrix.
// Stage: A 32K + G 8K + U 8K = 48K; 3 stages = 144K smem.
// ---------------------------------------------------------------------------
#define GU_STAGE_B 49152
__global__ __launch_bounds__(256, 1) void gateup_kernel(const int* __restrict__ counts)
{
    extern __shared__ __align__(1024) uint8_t smraw[];
    const uint32_t sb = smem_u32(smraw);
    const int tid = threadIdx.x, lane = tid & 31, warp = tid >> 5;
    const int gid = lane >> 2, tg = lane & 3;
    const int wm = (warp >> 1) * 64;   // 4 m-groups of 64
    const int wn = (warp & 1) * 32;    // 2 n-groups of 32 (per matrix)

    const int row0 = blockIdx.y * 256;
    const int n0   = blockIdx.x * 64;
    const int e = expert_of(counts, row0);

    const __half* Ap = g_x16 + (size_t)row0 * DIM;
    const __half* Gp = g_g16 + (size_t)e * HID * DIM + (size_t)n0 * DIM;
    const __half* Up = g_u16 + (size_t)e * HID * DIM + (size_t)n0 * DIM;

    auto issue = [&](int kt) {
        const int s = kt % STAGES;
        const uint32_t Ab = sb + s * GU_STAGE_B;
        const uint32_t Gb = Ab + 32768;
        const uint32_t Ub = Gb + 8192;
        const int k0 = kt * 64;
#pragma unroll
        for (int i = 0; i < 8; i++) {             // A: 2048 chunks
            int c = tid + i * 256; int r = c >> 3; int ch = c & 7;
            cpa16(tile_addr(Ab, r, ch), Ap + (size_t)r * DIM + k0 + ch * 8);
        }
#pragma unroll
        for (int i = 0; i < 2; i++) {             // G: 512 chunks
            int c = tid + i * 256; int r = c >> 3; int ch = c & 7;
            cpa16(tile_addr(Gb, r, ch), Gp + (size_t)r * DIM + k0 + ch * 8);
        }
#pragma unroll
        for (int i = 0; i < 2; i++) {             // U: 512 chunks
            int c = tid + i * 256; int r = c >> 3; int ch = c & 7;
            cpa16(tile_addr(Ub, r, ch), Up + (size_t)r * DIM + k0 + ch * 8);
        }
        CP_COMMIT();
    };

    for (int s = 0; s < STAGES - 1; s++) issue(s);

    float accg[4][4][4] = {};
    float accu[4][4][4] = {};

    const int a_row = lane & 15, a_ch = lane >> 4;
    const int b_row = (lane & 7) + ((lane & 16) >> 1), b_ch = (lane >> 3) & 1;

    const int NK = DIM / 64;   // 32
    for (int kt = 0; kt < NK; kt++) {
        CP_WAIT1();
        __syncthreads();
        if (kt + STAGES - 1 < NK) issue(kt + STAGES - 1);

        const int s = kt % STAGES;
        const uint32_t Ab = sb + s * GU_STAGE_B;
        const uint32_t Gb = Ab + 32768;
        const uint32_t Ub = Gb + 8192;
#pragma unroll
        for (int q = 0; q < 4; q++) {
            uint32_t af[4][4];
#pragma unroll
            for (int mi = 0; mi < 4; mi++)
                ldsm4(af[mi], tile_addr(Ab, wm + mi * 16 + a_row, 2 * q + a_ch));
            uint32_t bg[4][2], bu[4][2];
#pragma unroll
            for (int nj = 0; nj < 2; nj++) {
                uint32_t t4[4];
                ldsm4(t4, tile_addr(Gb, wn + nj * 16 + b_row, 2 * q + b_ch));
                bg[2 * nj][0] = t4[0]; bg[2 * nj][1] = t4[1];
                bg[2 * nj + 1][0] = t4[2]; bg[2 * nj + 1][1] = t4[3];
                ldsm4(t4, tile_addr(Ub, wn + nj * 16 + b_row, 2 * q + b_ch));
                bu[2 * nj][0] = t4[0]; bu[2 * nj][1] = t4[1];
                bu[2 * nj + 1][0] = t4[2]; bu[2 * nj + 1][1] = t4[3];
            }
#pragma unroll
            for (int ni = 0; ni < 4; ni++)
#pragma unroll
                for (int mi = 0; mi < 4; mi++) {
                    mma16816(accg[mi][ni], af[mi], bg[ni]);
                    mma16816(accu[mi][ni], af[mi], bu[ni]);
                }
        }
    }

    // SwiGLU epilogue -> fp16 h
#pragma unroll
    for (int mi = 0; mi < 4; mi++)
#pragma unroll
        for (int ni = 0; ni < 4; ni++) {
            int r = row0 + wm + mi * 16 + gid;
            int c = n0 + wn + ni * 8 + tg * 2;
            float g0 = accg[mi][ni][0], u0 = accu[mi][ni][0];
            float g1 = accg[mi][ni][1], u1 = accu[mi][ni][1];
            float g2 = accg[mi][ni][2], u2 = accu[mi][ni][2];
            float g3 = accg[mi][ni][3], u3 = accu[mi][ni][3];
            float h0 = g0 * u0 / (1.0f + __expf(-g0));
            float h1 = g1 * u1 / (1.0f + __expf(-g1));
            float h2 = g2 * u2 / (1.0f + __expf(-g2));
            float h3 = g3 * u3 / (1.0f + __expf(-g3));
            *reinterpret_cast<__half2*>(&g_h16[(size_t)r * HID + c]) =
                __float22half2_rn(make_float2(h0, h1));
            *reinterpret_cast<__half2*>(&g_h16[(size_t)(r + 8) * HID + c]) =
                __float22half2_rn(make_float2(h2, h3));
        }
}

// ---------------------------------------------------------------------------
// Kernel 2: down. out = h @ D_e^T. BM=128, BN=256, BK=64.
// 256 threads = 8 warps (2M x 4N), warp tile 64x64.
// Stage: A 16K + B 32K = 48K; 3 stages = 144K smem.
// ---------------------------------------------------------------------------
#define DN_STAGE_B 49152
__global__ __launch_bounds__(256, 1) void down_kernel(const int* __restrict__ counts,
                                                      float* __restrict__ out)
{
    extern __shared__ __align__(1024) uint8_t smraw[];
    const uint32_t sb = smem_u32(smraw);
    const int tid = threadIdx.x, lane = tid & 31, warp = tid >> 5;
    const int gid = lane >> 2, tg = lane & 3;
    const int wm = (warp >> 2) * 64;   // 2 m-groups of 64
    const int wn = (warp & 3) * 64;    // 4 n-groups of 64

    const int row0 = blockIdx.y * 128;
    const int n0   = blockIdx.x * 256;
    const int e = expert_of(counts, row0);

    const __half* Ap = g_h16 + (size_t)row0 * HID;
    const __half* Bp = g_d16 + (size_t)e * DIM * HID + (size_t)n0 * HID;

    auto issue = [&](int kt) {
        const int s = kt % STAGES;
        const uint32_t Ab = sb + s * DN_STAGE_B;
        const uint32_t Bb = Ab + 16384;
        const int k0 = kt * 64;
#pragma unroll
        for (int i = 0; i < 4; i++) {             // A: 1024 chunks
            int c = tid + i * 256; int r = c >> 3; int ch = c & 7;
            cpa16(tile_addr(Ab, r, ch), Ap + (size_t)r * HID + k0 + ch * 8);
        }
#pragma unroll
        for (int i = 0; i < 8; i++) {             // B: 2048 chunks
            int c = tid + i * 256; int r = c >> 3; int ch = c & 7;
            cpa16(tile_addr(Bb, r, ch), Bp + (size_t)r * HID + k0 + ch * 8);
        }
        CP_COMMIT();
    };

    for (int s = 0; s < STAGES - 1; s++) issue(s);

    float acc[4][8][4] = {};

    const int a_row = lane & 15, a_ch = lane >> 4;
    const int b_row = (lane & 7) + ((lane & 16) >> 1), b_ch = (lane >> 3) & 1;

    const int NK = HID / 64;   // 16
    for (int kt = 0; kt < NK; kt++) {
        CP_WAIT1();
        __syncthreads();
        if (kt + STAGES - 1 < NK) issue(kt + STAGES - 1);

        const int s = kt % STAGES;
        const uint32_t Ab = sb + s * DN_STAGE_B;
        const uint32_t Bb = Ab + 16384;
#pragma unroll
        for (int q = 0; q < 4; q++) {
            uint32_t af[4][4];
#pragma unroll
            for (int mi = 0; mi < 4; mi++)
                ldsm4(af[mi], tile_addr(Ab, wm + mi * 16 + a_row, 2 * q + a_ch));
            uint32_t bf[8][2];
#pragma unroll
            for (int nj = 0; nj < 4; nj++) {
                uint32_t t4[4];
                ldsm4(t4, tile_addr(Bb, wn + nj * 16 + b_row, 2 * q + b_ch));
                bf[2 * nj][0] = t4[0]; bf[2 * nj][1] = t4[1];
                bf[2 * nj + 1][0] = t4[2]; bf[2 * nj + 1][1] = t4[3];
            }
#pragma unroll
            for (int ni = 0; ni < 8; ni++)
#pragma unroll
                for (int mi = 0; mi < 4; mi++)
                    mma16816(acc[mi][ni], af[mi], bf[ni]);
        }
    }

#pragma unroll
    for (int mi = 0; mi < 4; mi++)
#pragma unroll
        for (int ni = 0; ni < 8; ni++) {
            int r = row0 + wm + mi * 16 + gid;
            int c = n0 + wn + ni * 8 + tg * 2;
            *reinterpret_cast<float2*>(&out[(size_t)r * DIM + c]) =
                make_float2(acc[mi][ni][0], acc[mi][ni][1]);
            *reinterpret_cast<float2*>(&out[(size_t)(r + 8) * DIM + c]) =
                make_float2(acc[mi][ni][2], acc[mi][ni][3]);
        }
}

extern "C" void kernel_launch(void* const* d_in, const int* in_sizes, int n_in,
                              void* d_out, int out_size) {
    const float* x      = (const float*)d_in[0];
    const float* gate   = (const float*)d_in[1];
    const float* up     = (const float*)d_in[2];
    const float* down   = (const float*)d_in[3];
    const int*   counts = (const int*)d_in[4];
    float* out = (float*)d_out;

    static bool attr_set = false;
    if (!attr_set) {
        cudaFuncSetAttribute(gateup_kernel, cudaFuncAttributeMaxDynamicSharedMemorySize,
                             STAGES * GU_STAGE_B);
        cudaFuncSetAttribute(down_kernel, cudaFuncAttributeMaxDynamicSharedMemorySize,
                             STAGES * DN_STAGE_B);
        attr_set = true;
    }

    __half* px; cudaGetSymbolAddress((void**)&px, g_x16);
    __half* pg; cudaGetSymbolAddress((void**)&pg, g_g16);
    __half* pu; cudaGetSymbolAddress((void**)&pu, g_u16);
    __half* pd; cudaGetSymbolAddress((void**)&pd, g_d16);

    const int CB = 1184;
    cvt_kernel<<<CB, 256>>>(x,    px, (size_t)TOTAL * DIM / 8);
    cvt_kernel<<<CB, 256>>>(gate, pg, (size_t)NEXP * HID * DIM / 8);
    cvt_kernel<<<CB, 256>>>(up,   pu, (size_t)NEXP * HID * DIM / 8);
    cvt_kernel<<<CB, 256>>>(down, pd, (size_t)NEXP * DIM * HID / 8);

    dim3 g1(HID / 64, TOTAL / 256);    // (16, 64)
    gateup_kernel<<<g1, 256, STAGES * GU_STAGE_B>>>(counts);

    dim3 g2(DIM / 256, TOTAL / 128);   // (8, 128)
    down_kernel<<<g2, 256, STAGES * DN_STAGE_B>>>(counts, out);
}